// round 4
// baseline (speedup 1.0000x reference)
#include <cuda_runtime.h>
#include <cstdint>

// Adaptive threshold spike encoding — TMA bulk-store version.
// x: [B=32, F=65536] f32.  out: [B=32, T=32, F=65536] f32.
// 2048 blocks x 256 threads, one float4 per thread (same mapping as best STG
// kernel), but stores are staged in SMEM and pushed with cp.async.bulk
// (4 KB per block per timestep), bypassing the L1 store pipeline.

#define TIMESTEPS 32
#define F_DIM 65536
#define RATE 0.1f
#define OMR 0.9f
#define THR0 0.5f
#define THREADS 256
#define CHUNK_BYTES 4096          // 256 threads * 16B

__global__ __launch_bounds__(THREADS)
void spike_tma_kernel(const float4* __restrict__ x, float* __restrict__ out) {
    __shared__ __align__(16) float4 buf[2][THREADS];

    int tid = threadIdx.x;
    int bid = blockIdx.x;
    int gid = bid * THREADS + tid;          // float4 index

    float4 xv = __ldcs(&x[gid]);

    int e  = gid << 2;                      // element index of lane 0
    int b  = e >> 16;                       // batch
    int f0 = (bid * (THREADS * 4)) & (F_DIM - 1);  // block's feature offset
    float* gbase = out + (size_t)b * (TIMESTEPS * F_DIM) + f0;

    float xx[4]  = {xv.x, xv.y, xv.z, xv.w};
    float ad[4], acc[4], thr[4];
#pragma unroll
    for (int l = 0; l < 4; l++) {
        ad[l]  = RATE * fabsf(xx[l]);
        acc[l] = 0.0f;
        thr[l] = THR0;
    }

    uint32_t sbase[2];
    sbase[0] = (uint32_t)__cvta_generic_to_shared(&buf[0][0]);
    sbase[1] = (uint32_t)__cvta_generic_to_shared(&buf[1][0]);

#pragma unroll
    for (int t = 0; t < TIMESTEPS; t++) {
        int pb = t & 1;
        // Before overwriting buffer pb, make sure the bulk store issued at
        // t-2 (which read this buffer) has consumed it.
        if (t >= 2 && tid == 0)
            asm volatile("cp.async.bulk.wait_group.read 1;" ::: "memory");
        __syncthreads();

        float s[4];
#pragma unroll
        for (int l = 0; l < 4; l++) {
            acc[l] = acc[l] + xx[l];
            bool m = (acc[l] >= thr[l]);
            s[l]   = m ? 1.0f : 0.0f;
            acc[l] = m ? 0.0f : acc[l];
            thr[l] = thr[l] * OMR + ad[l];
        }
        float4 sv;
        sv.x = s[0]; sv.y = s[1]; sv.z = s[2]; sv.w = s[3];
        buf[pb][tid] = sv;
        __syncthreads();

        if (tid == 0) {
            asm volatile("fence.proxy.async.shared::cta;" ::: "memory");
            asm volatile(
                "cp.async.bulk.global.shared::cta.bulk_group [%0], [%1], %2;"
                :: "l"(gbase + (size_t)t * F_DIM), "r"(sbase[pb]),
                   "n"(CHUNK_BYTES)
                : "memory");
            asm volatile("cp.async.bulk.commit_group;" ::: "memory");
        }
    }

    // Do not exit the CTA while bulk stores may still be reading its SMEM.
    if (tid == 0)
        asm volatile("cp.async.bulk.wait_group.read 0;" ::: "memory");
    __syncthreads();
}

extern "C" void kernel_launch(void* const* d_in, const int* in_sizes, int n_in,
                              void* d_out, int out_size) {
    const float4* x = (const float4*)d_in[0];
    float* out = (float*)d_out;
    int n4 = in_sizes[0] / 4;               // 524,288 float4
    int blocks = n4 / THREADS;              // 2048
    spike_tma_kernel<<<blocks, THREADS>>>(x, out);
}